// round 1
// baseline (speedup 1.0000x reference)
#include <cuda_runtime.h>
#include <cfloat>

// Problem constants (fixed by setup_inputs)
#define B_    128
#define K_    16
#define V_    50257
#define T_    20
#define H_    512
#define NROW  (B_ * K_)        // 2048 rows of logprobs
#define VPADW 12565            // u32 words per batch for counts ( >= V bytes / 4 )
#define CAP   4096             // candidate buffer capacity

// Output layout (float32, concatenated in reference return order)
#define O0 0                         // new_beam_seq          [B,T,K]  (40960)
#define O1 (B_ * T_ * K_)            // new_beam_seq_logprobs [B,T,K]  (40960)
#define O2 (2 * B_ * T_ * K_)        // sel_p                 [B,K]    (2048)
#define O3 (2 * B_ * T_ * K_ + B_ * K_) // new_state          [2,2,B,K,H] (4194304)

// Device scratch (no allocations allowed)
__device__ unsigned int g_cnt32[B_ * VPADW];   // packed uint8 diversity counts
__device__ float g_topv[NROW * K_];            // per-beam top-16 aug values (desc)
__device__ int   g_topi[NROW * K_];            // per-beam top-16 token ids
__device__ int   g_q[B_ * K_];                 // selected source beams
__device__ int   g_is64;                       // token dtype flag

// ---------------------------------------------------------------------------
// dtype detect: int64 tokens are all in [0,V); int32 data reinterpreted as
// int64 produces huge values with overwhelming probability.
__global__ void k_detect(const void* __restrict__ beam_seq) {
    const long long* p = (const long long*)beam_seq;
    int ok = 1;
    for (int i = 0; i < 8; i++) {
        long long v = p[i];
        if (v < 0 || v >= V_) ok = 0;
    }
    g_is64 = ok;
}

// ---------------------------------------------------------------------------
// counts: zero per-batch byte counts, then add 1 per prev-decision token.
__global__ void __launch_bounds__(256) k_counts(const void* __restrict__ prev) {
    int b = blockIdx.x;
    unsigned int* c = g_cnt32 + (size_t)b * VPADW;
    for (int i = threadIdx.x; i < VPADW; i += 256) c[i] = 0u;
    __syncthreads();
    int i = threadIdx.x;  // 16*K = 256 tokens per batch
    long long v = g_is64 ? ((const long long*)prev)[b * 256 + i]
                         : (long long)((const int*)prev)[b * 256 + i];
    int vi = (int)v;
    atomicAdd(&c[vi >> 2], 1u << ((vi & 3) * 8));
}

// ---------------------------------------------------------------------------
__device__ __forceinline__ bool better(float v1, int t1, float v2, int t2) {
    // jax.lax.top_k order: value descending, ties -> lower index first
    return (v1 > v2) || (v1 == v2 && t1 < t2);
}

// Exact block top-16 over buffer[0..n) plus the current shared top-16
// (appended at [n..n+16)).  256 threads. Leaves result sorted in s_tv/s_ti.
__device__ void select16(float* s_val, int* s_tok, int n,
                         float* s_tv, int* s_ti,
                         float* s_rv, int* s_rt, int* s_rp) {
    int tid = threadIdx.x;
    if (tid < 16) { s_val[n + tid] = s_tv[tid]; s_tok[n + tid] = s_ti[tid]; }
    __syncthreads();
    int m = n + 16;
    for (int r = 0; r < 16; r++) {
        float bv = -FLT_MAX; int bt = 0x7fffffff; int bp = -1;
        for (int p = tid; p < m; p += 256) {
            float v = s_val[p]; int tk = s_tok[p];
            if (better(v, tk, bv, bt)) { bv = v; bt = tk; bp = p; }
        }
        for (int off = 16; off; off >>= 1) {
            float ov = __shfl_down_sync(0xffffffffu, bv, off);
            int   ot = __shfl_down_sync(0xffffffffu, bt, off);
            int   op = __shfl_down_sync(0xffffffffu, bp, off);
            if (better(ov, ot, bv, bt)) { bv = ov; bt = ot; bp = op; }
        }
        if ((tid & 31) == 0) { s_rv[tid >> 5] = bv; s_rt[tid >> 5] = bt; s_rp[tid >> 5] = bp; }
        __syncthreads();
        if (tid == 0) {
            float Bv = s_rv[0]; int Bt = s_rt[0]; int Bp = s_rp[0];
            for (int w = 1; w < 8; w++)
                if (better(s_rv[w], s_rt[w], Bv, Bt)) { Bv = s_rv[w]; Bt = s_rt[w]; Bp = s_rp[w]; }
            s_tv[r] = Bv; s_ti[r] = Bt;
            if (Bp >= 0) s_val[Bp] = -FLT_MAX;   // remove winner
        }
        __syncthreads();
    }
}

// ---------------------------------------------------------------------------
// Per-(b,k) exact top-16 of aug = lp - 0.5*count (EOS -1000).
// Fast path: compare max of 8 RAW values against tau (penalties only lower
// values, so skipping max(raw) < tau is exact) -> counts only read on slow path.
__global__ void __launch_bounds__(256) k_topk(const float* __restrict__ logprobs) {
    __shared__ float s_val[CAP + 16];
    __shared__ int   s_tok[CAP + 16];
    __shared__ float s_tv[16];
    __shared__ int   s_ti[16];
    __shared__ int   s_cnt;
    __shared__ float s_rv[8];
    __shared__ int   s_rt[8], s_rp[8];

    int tid = threadIdx.x;
    int row = blockIdx.x;           // b*16 + k
    int b = row >> 4;
    const float* __restrict__ lp = logprobs + (size_t)row * V_;
    const unsigned char* __restrict__ cb =
        (const unsigned char*)g_cnt32 + (size_t)b * (VPADW * 4);

    if (tid < 16) { s_tv[tid] = -FLT_MAX; s_ti[tid] = 0x7fffffff; }
    if (tid == 0) s_cnt = 0;

    // Phase 0: first 2048 elements -> direct buffer fill, exact select.
#pragma unroll
    for (int j = 0; j < 8; j++) {
        int idx = j * 256 + tid;
        float aug = lp[idx] - 0.5f * (float)cb[idx];
        s_val[idx] = aug;
        s_tok[idx] = idx;
    }
    __syncthreads();
    select16(s_val, s_tok, 2048, s_tv, s_ti, s_rv, s_rt, s_rp);

    // Phase 1: stream remaining elements with threshold filter.
    for (int base0 = 2048; base0 < V_; base0 += 2048) {
        float thr = s_tv[15];
        if (base0 + 2048 <= V_) {
            float v[8];
#pragma unroll
            for (int j = 0; j < 8; j++) v[j] = lp[base0 + j * 256 + tid];
            float m01 = fmaxf(v[0], v[1]);
            float m23 = fmaxf(v[2], v[3]);
            float m45 = fmaxf(v[4], v[5]);
            float m67 = fmaxf(v[6], v[7]);
            float m = fmaxf(fmaxf(m01, m23), fmaxf(m45, m67));
            if (m >= thr) {
#pragma unroll
                for (int j = 0; j < 8; j++) {
                    int idx = base0 + j * 256 + tid;
                    float aug = v[j] - 0.5f * (float)cb[idx];
                    if (aug >= thr) {
                        int p = atomicAdd(&s_cnt, 1);
                        if (p < CAP) { s_val[p] = aug; s_tok[p] = idx; }
                    }
                }
            }
        } else {
            // tail (includes EOS index V-1)
#pragma unroll
            for (int j = 0; j < 8; j++) {
                int idx = base0 + j * 256 + tid;
                if (idx < V_) {
                    float val = lp[idx];
                    if (idx == V_ - 1) val -= 1000.0f;
                    float aug = val - 0.5f * (float)cb[idx];
                    if (aug >= thr) {
                        int p = atomicAdd(&s_cnt, 1);
                        if (p < CAP) { s_val[p] = aug; s_tok[p] = idx; }
                    }
                }
            }
        }
        __syncthreads();
        if (s_cnt > CAP - 2048) {     // headroom guarantee: never overflows
            int n = s_cnt; if (n > CAP) n = CAP;
            select16(s_val, s_tok, n, s_tv, s_ti, s_rv, s_rt, s_rp);
            if (tid == 0) s_cnt = 0;
            __syncthreads();
        }
    }
    __syncthreads();
    {
        int n = s_cnt; if (n > CAP) n = CAP;
        select16(s_val, s_tok, n, s_tv, s_ti, s_rv, s_rt, s_rp);
    }
    if (tid < 16) {
        g_topv[row * 16 + tid] = s_tv[tid];
        g_topi[row * 16 + tid] = s_ti[tid];
    }
}

// ---------------------------------------------------------------------------
// Per-batch: global top-16 over 256 candidates (sum + topv), flat-index
// tie-break; writes sel_p, row-t tokens/logprobs, and rewritten history.
__global__ void __launch_bounds__(256) k_select(
    const float* __restrict__ logprobs,
    const void*  __restrict__ beam_seq,
    const float* __restrict__ beam_lps,
    const float* __restrict__ sums,
    const void*  __restrict__ tin,
    float* __restrict__ out)
{
    __shared__ float cv[256 + 16];
    __shared__ int   ct[256 + 16];
    __shared__ float s_tv[16];
    __shared__ int   s_ti[16];
    __shared__ float s_rv[8];
    __shared__ int   s_rt[8], s_rp[8];
    __shared__ int   s_q[16], s_token[16];
    __shared__ float s_r[16];

    int b = blockIdx.x;
    int tid = threadIdx.x;

    cv[tid] = g_topv[b * 256 + tid] + sums[b * 16 + (tid >> 4)];
    ct[tid] = tid;                      // flat index = tie-break key
    if (tid < 16) { s_tv[tid] = -FLT_MAX; s_ti[tid] = 0x7fffffff; }
    __syncthreads();
    select16(cv, ct, 256, s_tv, s_ti, s_rv, s_rt, s_rp);

    int is64 = g_is64;
    if (tid < 16) {
        int flat = s_ti[tid];
        int q = flat >> 4;
        int token = g_topi[b * 256 + flat];
        float rr = logprobs[(size_t)(b * 16 + q) * V_ + token];  // unaug, exact
        if (token == V_ - 1) rr -= 1000.0f;
        s_q[tid] = q; s_token[tid] = token; s_r[tid] = rr;
        g_q[b * 16 + tid] = q;
        out[O2 + b * 16 + tid] = s_tv[tid];
    }
    __syncthreads();

    int t = ((const int*)tin)[0];   // little-endian low word works for i32/i64
    for (int idx = tid; idx < T_ * K_; idx += 256) {
        int rowi = idx >> 4, k2 = idx & 15;
        float sv, lv;
        if (rowi == t) {
            sv = (float)s_token[k2];
            lv = s_r[k2];
        } else {
            int kk = (rowi < t) ? s_q[k2] : k2;
            int off = (b * T_ + rowi) * K_ + kk;
            sv = is64 ? (float)((const long long*)beam_seq)[off]
                      : (float)((const int*)beam_seq)[off];
            lv = beam_lps[off];
        }
        out[O0 + b * (T_ * K_) + idx] = sv;
        out[O1 + b * (T_ * K_) + idx] = lv;
    }
}

// ---------------------------------------------------------------------------
// State gather along beam dim: out[s,l,b,k,:] = state[s,l,b,q[b,k],:]
__global__ void __launch_bounds__(128) k_state(const float* __restrict__ state,
                                               float* __restrict__ out) {
    int n = blockIdx.x;              // S*L*B*K = 8192
    int k  = n & 15;
    int b  = (n >> 4) & 127;
    int sl = n >> 11;                // 0..3 = s*2+l
    int q  = g_q[b * 16 + k];
    const float4* src = (const float4*)(state + ((((size_t)sl * B_) + b) * K_ + q) * H_);
    float4*       dst = (float4*)(out + O3 + ((((size_t)sl * B_) + b) * K_ + k) * H_);
    dst[threadIdx.x] = src[threadIdx.x];   // H=512 floats = 128 float4
}

// ---------------------------------------------------------------------------
extern "C" void kernel_launch(void* const* d_in, const int* in_sizes, int n_in,
                              void* d_out, int out_size) {
    const float* logprobs = (const float*)d_in[0];
    const void*  beam_seq = d_in[1];
    const float* beam_lps = (const float*)d_in[2];
    const float* sums     = (const float*)d_in[3];
    const float* state    = (const float*)d_in[4];
    const void*  prev     = d_in[5];
    const void*  tin      = d_in[6];
    float* out = (float*)d_out;

    k_detect<<<1, 1>>>(beam_seq);
    k_counts<<<B_, 256>>>(prev);
    k_topk<<<NROW, 256>>>(logprobs);
    k_select<<<B_, 256>>>(logprobs, beam_seq, beam_lps, sums, tin, out);
    k_state<<<2 * 2 * B_ * K_, 128>>>(state, out);
}

// round 2
// speedup vs baseline: 1.0003x; 1.0003x over previous
#include <cuda_runtime.h>
#include <cfloat>

// Problem constants (fixed by setup_inputs)
#define B_    128
#define K_    16
#define V_    50257
#define T_    20
#define H_    512
#define NROW  (B_ * K_)        // 2048 rows of logprobs
#define VPADW 12565            // u32 words per batch for counts ( >= V bytes / 4 )
#define CAP   4096             // candidate buffer capacity

// Output layout (float32, concatenated in reference return order)
#define O0 0                         // new_beam_seq          [B,T,K]  (40960)
#define O1 (B_ * T_ * K_)            // new_beam_seq_logprobs [B,T,K]  (40960)
#define O2 (2 * B_ * T_ * K_)        // sel_p                 [B,K]    (2048)
#define O3 (2 * B_ * T_ * K_ + B_ * K_) // new_state          [2,2,B,K,H] (4194304)

// Device scratch (no allocations allowed)
__device__ unsigned int g_cnt32[B_ * VPADW];   // packed uint8 diversity counts
__device__ float g_topv[NROW * K_];            // per-beam top-16 aug values (desc)
__device__ int   g_topi[NROW * K_];            // per-beam top-16 token ids
__device__ int   g_q[B_ * K_];                 // selected source beams
__device__ int   g_is64;                       // token dtype flag

// ---------------------------------------------------------------------------
// dtype detect: int64 tokens are all in [0,V); int32 data reinterpreted as
// int64 produces huge values with overwhelming probability.
__global__ void k_detect(const void* __restrict__ beam_seq) {
    const long long* p = (const long long*)beam_seq;
    int ok = 1;
    for (int i = 0; i < 8; i++) {
        long long v = p[i];
        if (v < 0 || v >= V_) ok = 0;
    }
    g_is64 = ok;
}

// ---------------------------------------------------------------------------
// counts: zero per-batch byte counts, then add 1 per prev-decision token.
__global__ void __launch_bounds__(256) k_counts(const void* __restrict__ prev) {
    int b = blockIdx.x;
    unsigned int* c = g_cnt32 + (size_t)b * VPADW;
    for (int i = threadIdx.x; i < VPADW; i += 256) c[i] = 0u;
    __syncthreads();
    int i = threadIdx.x;  // 16*K = 256 tokens per batch
    long long v = g_is64 ? ((const long long*)prev)[b * 256 + i]
                         : (long long)((const int*)prev)[b * 256 + i];
    int vi = (int)v;
    atomicAdd(&c[vi >> 2], 1u << ((vi & 3) * 8));
}

// ---------------------------------------------------------------------------
__device__ __forceinline__ bool better(float v1, int t1, float v2, int t2) {
    // jax.lax.top_k order: value descending, ties -> lower index first
    return (v1 > v2) || (v1 == v2 && t1 < t2);
}

// Exact block top-16 over buffer[0..n) plus the current shared top-16
// (appended at [n..n+16)).  256 threads. Leaves result sorted in s_tv/s_ti.
__device__ void select16(float* s_val, int* s_tok, int n,
                         float* s_tv, int* s_ti,
                         float* s_rv, int* s_rt, int* s_rp) {
    int tid = threadIdx.x;
    if (tid < 16) { s_val[n + tid] = s_tv[tid]; s_tok[n + tid] = s_ti[tid]; }
    __syncthreads();
    int m = n + 16;
    for (int r = 0; r < 16; r++) {
        float bv = -FLT_MAX; int bt = 0x7fffffff; int bp = -1;
        for (int p = tid; p < m; p += 256) {
            float v = s_val[p]; int tk = s_tok[p];
            if (better(v, tk, bv, bt)) { bv = v; bt = tk; bp = p; }
        }
        for (int off = 16; off; off >>= 1) {
            float ov = __shfl_down_sync(0xffffffffu, bv, off);
            int   ot = __shfl_down_sync(0xffffffffu, bt, off);
            int   op = __shfl_down_sync(0xffffffffu, bp, off);
            if (better(ov, ot, bv, bt)) { bv = ov; bt = ot; bp = op; }
        }
        if ((tid & 31) == 0) { s_rv[tid >> 5] = bv; s_rt[tid >> 5] = bt; s_rp[tid >> 5] = bp; }
        __syncthreads();
        if (tid == 0) {
            float Bv = s_rv[0]; int Bt = s_rt[0]; int Bp = s_rp[0];
            for (int w = 1; w < 8; w++)
                if (better(s_rv[w], s_rt[w], Bv, Bt)) { Bv = s_rv[w]; Bt = s_rt[w]; Bp = s_rp[w]; }
            s_tv[r] = Bv; s_ti[r] = Bt;
            if (Bp >= 0) s_val[Bp] = -FLT_MAX;   // remove winner
        }
        __syncthreads();
    }
}

// ---------------------------------------------------------------------------
// Per-(b,k) exact top-16 of aug = lp - 0.5*count (EOS -1000).
// Fast path: compare max of 8 RAW values against tau (penalties only lower
// values, so skipping max(raw) < tau is exact) -> counts only read on slow path.
__global__ void __launch_bounds__(256) k_topk(const float* __restrict__ logprobs) {
    __shared__ float s_val[CAP + 16];
    __shared__ int   s_tok[CAP + 16];
    __shared__ float s_tv[16];
    __shared__ int   s_ti[16];
    __shared__ int   s_cnt;
    __shared__ float s_rv[8];
    __shared__ int   s_rt[8], s_rp[8];

    int tid = threadIdx.x;
    int row = blockIdx.x;           // b*16 + k
    int b = row >> 4;
    const float* __restrict__ lp = logprobs + (size_t)row * V_;
    const unsigned char* __restrict__ cb =
        (const unsigned char*)g_cnt32 + (size_t)b * (VPADW * 4);

    if (tid < 16) { s_tv[tid] = -FLT_MAX; s_ti[tid] = 0x7fffffff; }
    if (tid == 0) s_cnt = 0;

    // Phase 0: first 2048 elements -> direct buffer fill, exact select.
#pragma unroll
    for (int j = 0; j < 8; j++) {
        int idx = j * 256 + tid;
        float aug = lp[idx] - 0.5f * (float)cb[idx];
        s_val[idx] = aug;
        s_tok[idx] = idx;
    }
    __syncthreads();
    select16(s_val, s_tok, 2048, s_tv, s_ti, s_rv, s_rt, s_rp);

    // Phase 1: stream remaining elements with threshold filter.
    for (int base0 = 2048; base0 < V_; base0 += 2048) {
        float thr = s_tv[15];
        if (base0 + 2048 <= V_) {
            float v[8];
#pragma unroll
            for (int j = 0; j < 8; j++) v[j] = lp[base0 + j * 256 + tid];
            float m01 = fmaxf(v[0], v[1]);
            float m23 = fmaxf(v[2], v[3]);
            float m45 = fmaxf(v[4], v[5]);
            float m67 = fmaxf(v[6], v[7]);
            float m = fmaxf(fmaxf(m01, m23), fmaxf(m45, m67));
            if (m >= thr) {
#pragma unroll
                for (int j = 0; j < 8; j++) {
                    int idx = base0 + j * 256 + tid;
                    float aug = v[j] - 0.5f * (float)cb[idx];
                    if (aug >= thr) {
                        int p = atomicAdd(&s_cnt, 1);
                        if (p < CAP) { s_val[p] = aug; s_tok[p] = idx; }
                    }
                }
            }
        } else {
            // tail (includes EOS index V-1)
#pragma unroll
            for (int j = 0; j < 8; j++) {
                int idx = base0 + j * 256 + tid;
                if (idx < V_) {
                    float val = lp[idx];
                    if (idx == V_ - 1) val -= 1000.0f;
                    float aug = val - 0.5f * (float)cb[idx];
                    if (aug >= thr) {
                        int p = atomicAdd(&s_cnt, 1);
                        if (p < CAP) { s_val[p] = aug; s_tok[p] = idx; }
                    }
                }
            }
        }
        __syncthreads();
        if (s_cnt > CAP - 2048) {     // headroom guarantee: never overflows
            int n = s_cnt; if (n > CAP) n = CAP;
            select16(s_val, s_tok, n, s_tv, s_ti, s_rv, s_rt, s_rp);
            if (tid == 0) s_cnt = 0;
            __syncthreads();
        }
    }
    __syncthreads();
    {
        int n = s_cnt; if (n > CAP) n = CAP;
        select16(s_val, s_tok, n, s_tv, s_ti, s_rv, s_rt, s_rp);
    }
    if (tid < 16) {
        g_topv[row * 16 + tid] = s_tv[tid];
        g_topi[row * 16 + tid] = s_ti[tid];
    }
}

// ---------------------------------------------------------------------------
// Per-batch: global top-16 over 256 candidates (sum + topv), flat-index
// tie-break; writes sel_p, row-t tokens/logprobs, and rewritten history.
__global__ void __launch_bounds__(256) k_select(
    const float* __restrict__ logprobs,
    const void*  __restrict__ beam_seq,
    const float* __restrict__ beam_lps,
    const float* __restrict__ sums,
    const void*  __restrict__ tin,
    float* __restrict__ out)
{
    __shared__ float cv[256 + 16];
    __shared__ int   ct[256 + 16];
    __shared__ float s_tv[16];
    __shared__ int   s_ti[16];
    __shared__ float s_rv[8];
    __shared__ int   s_rt[8], s_rp[8];
    __shared__ int   s_q[16], s_token[16];
    __shared__ float s_r[16];

    int b = blockIdx.x;
    int tid = threadIdx.x;

    cv[tid] = g_topv[b * 256 + tid] + sums[b * 16 + (tid >> 4)];
    ct[tid] = tid;                      // flat index = tie-break key
    if (tid < 16) { s_tv[tid] = -FLT_MAX; s_ti[tid] = 0x7fffffff; }
    __syncthreads();
    select16(cv, ct, 256, s_tv, s_ti, s_rv, s_rt, s_rp);

    int is64 = g_is64;
    if (tid < 16) {
        int flat = s_ti[tid];
        int q = flat >> 4;
        int token = g_topi[b * 256 + flat];
        float rr = logprobs[(size_t)(b * 16 + q) * V_ + token];  // unaug, exact
        if (token == V_ - 1) rr -= 1000.0f;
        s_q[tid] = q; s_token[tid] = token; s_r[tid] = rr;
        g_q[b * 16 + tid] = q;
        out[O2 + b * 16 + tid] = s_tv[tid];
    }
    __syncthreads();

    int t = ((const int*)tin)[0];   // little-endian low word works for i32/i64
    for (int idx = tid; idx < T_ * K_; idx += 256) {
        int rowi = idx >> 4, k2 = idx & 15;
        float sv, lv;
        if (rowi == t) {
            sv = (float)s_token[k2];
            lv = s_r[k2];
        } else {
            int kk = (rowi < t) ? s_q[k2] : k2;
            int off = (b * T_ + rowi) * K_ + kk;
            sv = is64 ? (float)((const long long*)beam_seq)[off]
                      : (float)((const int*)beam_seq)[off];
            lv = beam_lps[off];
        }
        out[O0 + b * (T_ * K_) + idx] = sv;
        out[O1 + b * (T_ * K_) + idx] = lv;
    }
}

// ---------------------------------------------------------------------------
// State gather along beam dim: out[s,l,b,k,:] = state[s,l,b,q[b,k],:]
__global__ void __launch_bounds__(128) k_state(const float* __restrict__ state,
                                               float* __restrict__ out) {
    int n = blockIdx.x;              // S*L*B*K = 8192
    int k  = n & 15;
    int b  = (n >> 4) & 127;
    int sl = n >> 11;                // 0..3 = s*2+l
    int q  = g_q[b * 16 + k];
    const float4* src = (const float4*)(state + ((((size_t)sl * B_) + b) * K_ + q) * H_);
    float4*       dst = (float4*)(out + O3 + ((((size_t)sl * B_) + b) * K_ + k) * H_);
    dst[threadIdx.x] = src[threadIdx.x];   // H=512 floats = 128 float4
}

// ---------------------------------------------------------------------------
extern "C" void kernel_launch(void* const* d_in, const int* in_sizes, int n_in,
                              void* d_out, int out_size) {
    const float* logprobs = (const float*)d_in[0];
    const void*  beam_seq = d_in[1];
    const float* beam_lps = (const float*)d_in[2];
    const float* sums     = (const float*)d_in[3];
    const float* state    = (const float*)d_in[4];
    const void*  prev     = d_in[5];
    const void*  tin      = d_in[6];
    float* out = (float*)d_out;

    k_detect<<<1, 1>>>(beam_seq);
    k_counts<<<B_, 256>>>(prev);
    k_topk<<<NROW, 256>>>(logprobs);
    k_select<<<B_, 256>>>(logprobs, beam_seq, beam_lps, sums, tin, out);
    k_state<<<2 * 2 * B_ * K_, 128>>>(state, out);
}

// round 3
// speedup vs baseline: 1.1670x; 1.1667x over previous
#include <cuda_runtime.h>
#include <cfloat>

#define B_    128
#define K_    16
#define V_    50257
#define T_    20
#define H_    512
#define NROW  2048
#define VPADW 12565

#define O0 0
#define O1 (B_ * T_ * K_)
#define O2 (2 * B_ * T_ * K_)
#define O3 (2 * B_ * T_ * K_ + B_ * K_)

#define BUFCAP 1024

__device__ unsigned int       g_cnt32[B_ * VPADW];  // packed uint8 diversity counts
__device__ unsigned long long g_key[NROW * 16];     // per-row sorted top-16 keys
__device__ int                g_q[B_ * K_];
__device__ int                g_is64;

// ---------------------------------------------------------------------------
__device__ __forceinline__ unsigned ford(float v) {
    unsigned u = __float_as_uint(v);
    return (u & 0x80000000u) ? ~u : (u | 0x80000000u);
}
__device__ __forceinline__ float funord(unsigned u) {
    return __uint_as_float((u & 0x80000000u) ? (u ^ 0x80000000u) : ~u);
}
// key: value desc primary, token asc secondary (larger key = better)
__device__ __forceinline__ unsigned long long mkkey(float v, int tok) {
    return ((unsigned long long)ford(v) << 32) | (unsigned)(~(unsigned)tok);
}

__device__ __forceinline__ int blk_sum(int c, int* s_ws) {
    int tid = threadIdx.x;
    c = (int)__reduce_add_sync(0xffffffffu, (unsigned)c);
    if ((tid & 31) == 0) s_ws[tid >> 5] = c;
    __syncthreads();
    int t = s_ws[0] + s_ws[1] + s_ws[2] + s_ws[3] + s_ws[4] + s_ws[5] + s_ws[6] + s_ws[7];
    __syncthreads();
    return t;
}

// ---------------------------------------------------------------------------
// prep: dtype detect + zero/build per-batch diversity counts
__global__ void __launch_bounds__(256) k_prep(const void* __restrict__ prev,
                                              const void* __restrict__ beam_seq) {
    int b = blockIdx.x, tid = threadIdx.x;
    __shared__ int s_is64;
    if (tid == 0) {
        const long long* p = (const long long*)prev;
        int ok = 1;
        for (int i = 0; i < 8; i++) { long long v = p[i]; if (v < 0 || v >= V_) ok = 0; }
        s_is64 = ok;
        if (b == 0) {
            const long long* q = (const long long*)beam_seq;
            int ok2 = 1;
            for (int i = 0; i < 8; i++) { long long v = q[i]; if (v < 0 || v >= V_) ok2 = 0; }
            g_is64 = ok2;
        }
    }
    unsigned int* c = g_cnt32 + (size_t)b * VPADW;
    for (int i = tid; i < VPADW; i += 256) c[i] = 0u;
    __syncthreads();
    long long v = s_is64 ? ((const long long*)prev)[b * 256 + tid]
                         : (long long)((const int*)prev)[b * 256 + tid];
    int vi = (int)v;
    atomicAdd(&c[vi >> 2], 1u << ((vi & 3) * 8));
}

// ---------------------------------------------------------------------------
// per-row exact top-16 of aug = lp - 0.5*count (EOS -1000 at V-1)
__global__ void __launch_bounds__(256) k_topk(const float* __restrict__ logprobs) {
    __shared__ unsigned long long s_buf[BUFCAP];
    __shared__ int s_ws[8];
    __shared__ int s_cnt, s_ovf, s_snap;

    int tid = threadIdx.x;
    int row = blockIdx.x;
    int b = row >> 4;
    const float* __restrict__ lp = logprobs + (size_t)row * V_;
    const unsigned char* __restrict__ cb =
        (const unsigned char*)g_cnt32 + (size_t)b * (VPADW * 4);

    int pad = (4 - (row & 3)) & 3;                    // 16B-align float4 stream
    const float4* __restrict__ lp4 = (const float4*)(lp + pad);

    if (tid == 0) { s_cnt = 0; s_ovf = 0; }
    __syncthreads();

    // ---- seed: elements [pad, pad+4096), 16 per thread in registers ----
    float vv[16];
#pragma unroll
    for (int j = 0; j < 4; j++) {
        float4 A = lp4[j * 256 + tid];
        vv[4 * j] = A.x; vv[4 * j + 1] = A.y; vv[4 * j + 2] = A.z; vv[4 * j + 3] = A.w;
    }
    float aug[16];
#pragma unroll
    for (int j = 0; j < 16; j++) {
        int idx = pad + (j >> 2) * 1024 + 4 * tid + (j & 3);
        aug[j] = vv[j] - 0.5f * (float)cb[idx];
    }
    float lo = -1200.f, hi = 0.f;
    for (int it = 0; it < 30; it++) {
        float mid = 0.5f * (lo + hi);
        int c = 0;
#pragma unroll
        for (int j = 0; j < 16; j++) c += (aug[j] >= mid);
        int tot = blk_sum(c, s_ws);
        if (tot >= 16) { lo = mid; if (tot <= 48) break; }
        else hi = mid;
    }
    float thr = lo;
#pragma unroll
    for (int j = 0; j < 16; j++) {
        if (aug[j] >= thr) {
            int idx = pad + (j >> 2) * 1024 + 4 * tid + (j & 3);
            int p = atomicAdd(&s_cnt, 1);
            if (p < BUFCAP) s_buf[p] = mkkey(aug[j], idx); else s_ovf = 1;
        }
    }
    if (tid < pad) {                                  // [0,pad) scalar prologue
        float a = lp[tid] - 0.5f * (float)cb[tid];
        int p = atomicAdd(&s_cnt, 1);
        if (p < BUFCAP) s_buf[p] = mkkey(a, tid); else s_ovf = 1;
    }
    __syncthreads();

    // ---- stream full chunks of 4096 ----
    int base = pad + 4096;
    for (; base + 4096 <= V_; base += 4096) {
        const float4* p4 = (const float4*)(lp + base);
#pragma unroll
        for (int j = 0; j < 4; j++) {
            float4 A = p4[j * 256 + tid];
            vv[4 * j] = A.x; vv[4 * j + 1] = A.y; vv[4 * j + 2] = A.z; vv[4 * j + 3] = A.w;
        }
        while (true) {
            if (tid == 0) s_snap = s_cnt;
            __syncthreads();
#pragma unroll
            for (int j = 0; j < 4; j++) {
                float m = fmaxf(fmaxf(vv[4 * j], vv[4 * j + 1]),
                                fmaxf(vv[4 * j + 2], vv[4 * j + 3]));
                if (m >= thr) {
#pragma unroll
                    for (int e = 0; e < 4; e++) {
                        float v = vv[4 * j + e];
                        if (v >= thr) {
                            int idx = base + j * 1024 + 4 * tid + e;
                            float a = v - 0.5f * (float)cb[idx];
                            if (a >= thr) {
                                int p = atomicAdd(&s_cnt, 1);
                                if (p < BUFCAP) s_buf[p] = mkkey(a, idx); else s_ovf = 1;
                            }
                        }
                    }
                }
            }
            __syncthreads();
            if (!s_ovf) break;
            // rollback + tighten (rare): raise thr over buffer[0..snap] + regs
            if (tid == 0) { s_cnt = s_snap; s_ovf = 0; }
            __syncthreads();
            int snap = s_snap;
            float tlo = thr, thi = 0.f;
            for (int it = 0; it < 30; it++) {
                float mid = 0.5f * (tlo + thi);
                unsigned long long km = ((unsigned long long)ford(mid)) << 32;
                int c = 0;
                for (int p = tid; p < snap; p += 256) c += (s_buf[p] >= km);
#pragma unroll
                for (int j = 0; j < 16; j++) {
                    float v = vv[j];
                    if (v >= mid) {
                        int idx = base + (j >> 2) * 1024 + 4 * tid + (j & 3);
                        float a = v - 0.5f * (float)cb[idx];
                        c += (a >= mid);
                    }
                }
                int tot = blk_sum(c, s_ws);
                if (tot >= 16) { tlo = mid; if (tot <= BUFCAP / 2) break; }
                else thi = mid;
            }
            thr = tlo;
            // in-place compact buffer
            unsigned long long keep[4]; int nk = 0;
            unsigned long long kt = ((unsigned long long)ford(thr)) << 32;
            for (int p = tid; p < snap; p += 256) {
                unsigned long long k = s_buf[p];
                if (k >= kt && nk < 4) keep[nk++] = k;
            }
            __syncthreads();
            if (tid == 0) s_cnt = 0;
            __syncthreads();
            for (int i = 0; i < nk; i++) { int p = atomicAdd(&s_cnt, 1); s_buf[p] = keep[i]; }
            __syncthreads();
        }
    }

    // ---- tail (< 4096 elements, includes EOS at V-1) ----
    while (true) {
        if (tid == 0) s_snap = s_cnt;
        __syncthreads();
        for (int idx = base + tid; idx < V_; idx += 256) {
            float v = lp[idx];
            if (idx == V_ - 1) v -= 1000.0f;
            if (v >= thr) {
                float a = v - 0.5f * (float)cb[idx];
                if (a >= thr) {
                    int p = atomicAdd(&s_cnt, 1);
                    if (p < BUFCAP) s_buf[p] = mkkey(a, idx); else s_ovf = 1;
                }
            }
        }
        __syncthreads();
        if (!s_ovf) break;
        if (tid == 0) { s_cnt = s_snap; s_ovf = 0; }
        __syncthreads();
        int snap = s_snap;
        float tlo = thr, thi = 0.f;
        for (int it = 0; it < 30; it++) {
            float mid = 0.5f * (tlo + thi);
            unsigned long long km = ((unsigned long long)ford(mid)) << 32;
            int c = 0;
            for (int p = tid; p < snap; p += 256) c += (s_buf[p] >= km);
            for (int idx = base + tid; idx < V_; idx += 256) {
                float v = lp[idx];
                if (idx == V_ - 1) v -= 1000.0f;
                if (v >= mid) {
                    float a = v - 0.5f * (float)cb[idx];
                    c += (a >= mid);
                }
            }
            int tot = blk_sum(c, s_ws);
            if (tot >= 16) { tlo = mid; if (tot <= BUFCAP / 2) break; }
            else thi = mid;
        }
        thr = tlo;
        unsigned long long keep[4]; int nk = 0;
        unsigned long long kt = ((unsigned long long)ford(thr)) << 32;
        for (int p = tid; p < snap; p += 256) {
            unsigned long long k = s_buf[p];
            if (k >= kt && nk < 4) keep[nk++] = k;
        }
        __syncthreads();
        if (tid == 0) s_cnt = 0;
        __syncthreads();
        for (int i = 0; i < nk; i++) { int p = atomicAdd(&s_cnt, 1); s_buf[p] = keep[i]; }
        __syncthreads();
    }

    // ---- exact top-16 via rank selection (unique u64 keys) ----
    int n = s_cnt; if (n > BUFCAP) n = BUFCAP;
    for (int i = tid; i < n; i += 256) {
        unsigned long long k = s_buf[i];
        int r = 0;
        for (int p = 0; p < n; p++) r += (s_buf[p] > k);
        if (r < 16) g_key[row * 16 + r] = k;
    }
}

// ---------------------------------------------------------------------------
// per-batch global top-16 over 256 candidates; writes sel_p + history rewrite
__global__ void __launch_bounds__(256) k_select(
        const float* __restrict__ logprobs,
        const void*  __restrict__ beam_seq,
        const float* __restrict__ beam_lps,
        const float* __restrict__ sums,
        const void*  __restrict__ tin,
        float* __restrict__ out) {
    __shared__ unsigned long long s_k2[256];
    __shared__ int s_q[16], s_token[16];
    __shared__ float s_r[16];

    int b = blockIdx.x, tid = threadIdx.x;
    unsigned long long k = g_key[b * 256 + tid];
    float augv = funord((unsigned)(k >> 32));
    int tok = (int)(~(unsigned)k);
    float comb = augv + sums[b * 16 + (tid >> 4)];
    // global key: comb desc, flat idx asc (flat = tid = q*16 + col)
    unsigned long long k2 = ((unsigned long long)ford(comb) << 32) | (unsigned)(255 - tid);
    s_k2[tid] = k2;
    __syncthreads();
    int r = 0;
    for (int p = 0; p < 256; p++) r += (s_k2[p] > k2);
    if (r < 16) {
        int q = tid >> 4;
        float rr = logprobs[(size_t)(b * 16 + q) * V_ + tok];
        if (tok == V_ - 1) rr -= 1000.0f;
        s_q[r] = q; s_token[r] = tok; s_r[r] = rr;
        g_q[b * 16 + r] = q;
        out[O2 + b * 16 + r] = comb;
    }
    __syncthreads();

    int is64 = g_is64;
    int t = ((const int*)tin)[0];     // low 32 LE word valid for i32/i64
    for (int idx = tid; idx < T_ * K_; idx += 256) {
        int rowi = idx >> 4, k2i = idx & 15;
        float sv, lv;
        if (rowi == t) {
            sv = (float)s_token[k2i];
            lv = s_r[k2i];
        } else {
            int kk = (rowi < t) ? s_q[k2i] : k2i;
            int off = (b * T_ + rowi) * K_ + kk;
            sv = is64 ? (float)((const long long*)beam_seq)[off]
                      : (float)((const int*)beam_seq)[off];
            lv = beam_lps[off];
        }
        out[O0 + b * (T_ * K_) + idx] = sv;
        out[O1 + b * (T_ * K_) + idx] = lv;
    }
}

// ---------------------------------------------------------------------------
__global__ void __launch_bounds__(128) k_state(const float* __restrict__ state,
                                               float* __restrict__ out) {
    int n = blockIdx.x;
    int k  = n & 15;
    int b  = (n >> 4) & 127;
    int sl = n >> 11;
    int q  = g_q[b * 16 + k];
    const float4* src = (const float4*)(state + ((((size_t)sl * B_) + b) * K_ + q) * H_);
    float4*       dst = (float4*)(out + O3 + ((((size_t)sl * B_) + b) * K_ + k) * H_);
    dst[threadIdx.x] = src[threadIdx.x];
}

// ---------------------------------------------------------------------------
extern "C" void kernel_launch(void* const* d_in, const int* in_sizes, int n_in,
                              void* d_out, int out_size) {
    const float* logprobs = (const float*)d_in[0];
    const void*  beam_seq = d_in[1];
    const float* beam_lps = (const float*)d_in[2];
    const float* sums     = (const float*)d_in[3];
    const float* state    = (const float*)d_in[4];
    const void*  prev     = d_in[5];
    const void*  tin      = d_in[6];
    float* out = (float*)d_out;

    k_prep<<<B_, 256>>>(prev, beam_seq);
    k_topk<<<NROW, 256>>>(logprobs);
    k_select<<<B_, 256>>>(logprobs, beam_seq, beam_lps, sums, tin, out);
    k_state<<<2 * 2 * B_ * K_, 128>>>(state, out);
}

// round 5
// speedup vs baseline: 1.8928x; 1.6219x over previous
#include <cuda_runtime.h>
#include <cfloat>
#include <math_constants.h>

#define B_    128
#define K_    16
#define V_    50257
#define T_    20
#define H_    512
#define NROW  2048
#define VPADW 12565

#define O0 0
#define O1 (B_ * T_ * K_)
#define O2 (2 * B_ * T_ * K_)
#define O3 (2 * B_ * T_ * K_ + B_ * K_)

#define BUFCAP 2048

__device__ unsigned int       g_cnt32[B_ * VPADW];  // packed uint8 diversity counts
__device__ unsigned long long g_key[NROW * 16];     // per-row sorted top-16 keys
__device__ int                g_q[B_ * K_];
__device__ int                g_is64;

// ---------------------------------------------------------------------------
__device__ __forceinline__ unsigned ford(float v) {
    unsigned u = __float_as_uint(v);
    return (u & 0x80000000u) ? ~u : (u | 0x80000000u);
}
__device__ __forceinline__ float funord(unsigned u) {
    return __uint_as_float((u & 0x80000000u) ? (u ^ 0x80000000u) : ~u);
}
// key: value desc primary, token asc secondary (larger key = better)
__device__ __forceinline__ unsigned long long mkkey(float v, int tok) {
    return ((unsigned long long)ford(v) << 32) | (unsigned)(~(unsigned)tok);
}

__device__ __forceinline__ int blk_sum(int c, int* s_ws) {
    int tid = threadIdx.x;
    c = (int)__reduce_add_sync(0xffffffffu, (unsigned)c);
    if ((tid & 31) == 0) s_ws[tid >> 5] = c;
    __syncthreads();
    int t = s_ws[0] + s_ws[1] + s_ws[2] + s_ws[3] + s_ws[4] + s_ws[5] + s_ws[6] + s_ws[7];
    __syncthreads();
    return t;
}

// ---------------------------------------------------------------------------
__global__ void __launch_bounds__(256) k_prep(const void* __restrict__ prev,
                                              const void* __restrict__ beam_seq) {
    int b = blockIdx.x, tid = threadIdx.x;
    __shared__ int s_is64;
    if (tid == 0) {
        const long long* p = (const long long*)prev;
        int ok = 1;
        for (int i = 0; i < 8; i++) { long long v = p[i]; if (v < 0 || v >= V_) ok = 0; }
        s_is64 = ok;
        if (b == 0) {
            const long long* q = (const long long*)beam_seq;
            int ok2 = 1;
            for (int i = 0; i < 8; i++) { long long v = q[i]; if (v < 0 || v >= V_) ok2 = 0; }
            g_is64 = ok2;
        }
    }
    unsigned int* c = g_cnt32 + (size_t)b * VPADW;
    for (int i = tid; i < VPADW; i += 256) c[i] = 0u;
    __syncthreads();
    long long v = s_is64 ? ((const long long*)prev)[b * 256 + tid]
                         : (long long)((const int*)prev)[b * 256 + tid];
    int vi = (int)v;
    atomicAdd(&c[vi >> 2], 1u << ((vi & 3) * 8));
}

// ---------------------------------------------------------------------------
__device__ __forceinline__ void pquad(float4 A, int fidx, float thr,
        const unsigned char* __restrict__ cb,
        unsigned long long* s_buf, int* s_cnt, int* s_ovf) {
    float m = fmaxf(fmaxf(A.x, A.y), fmaxf(A.z, A.w));
    if (m < thr) return;
    float v0 = A.x, v1 = A.y, v2 = A.z, v3 = A.w;
    if (v0 >= thr) { float a = v0 - 0.5f * (float)cb[fidx];     if (a >= thr) { int p = atomicAdd(s_cnt, 1); if (p < BUFCAP) s_buf[p] = mkkey(a, fidx);     else *s_ovf = 1; } }
    if (v1 >= thr) { float a = v1 - 0.5f * (float)cb[fidx + 1]; if (a >= thr) { int p = atomicAdd(s_cnt, 1); if (p < BUFCAP) s_buf[p] = mkkey(a, fidx + 1); else *s_ovf = 1; } }
    if (v2 >= thr) { float a = v2 - 0.5f * (float)cb[fidx + 2]; if (a >= thr) { int p = atomicAdd(s_cnt, 1); if (p < BUFCAP) s_buf[p] = mkkey(a, fidx + 2); else *s_ovf = 1; } }
    if (v3 >= thr) { float a = v3 - 0.5f * (float)cb[fidx + 3]; if (a >= thr) { int p = atomicAdd(s_cnt, 1); if (p < BUFCAP) s_buf[p] = mkkey(a, fidx + 3); else *s_ovf = 1; } }
}

// per-row exact top-16 of aug = lp - 0.5*count (EOS -1000 at V-1)
__global__ void __launch_bounds__(256) k_topk(const float* __restrict__ logprobs) {
    __shared__ unsigned long long s_buf[BUFCAP];
    __shared__ unsigned long long s_b2[256];
    __shared__ int s_ws[8];
    __shared__ int s_cnt, s_ovf, s_cnt2;

    int tid = threadIdx.x;
    int row = blockIdx.x;
    int b = row >> 4;
    const float* __restrict__ lp = logprobs + (size_t)row * V_;
    const unsigned char* __restrict__ cb =
        (const unsigned char*)g_cnt32 + (size_t)b * (VPADW * 4);

    int pad = (4 - (row & 3)) & 3;                    // 16B-align float4 stream
    const float4* __restrict__ lp4 = (const float4*)(lp + pad);

    if (tid == 0) { s_cnt = 0; s_ovf = 0; }

    // ---- seed: [pad, pad+4096), 16 per thread, aug in registers ----
    float vv[16];
#pragma unroll
    for (int j = 0; j < 4; j++) {
        float4 A = lp4[j * 256 + tid];
        vv[4 * j] = A.x; vv[4 * j + 1] = A.y; vv[4 * j + 2] = A.z; vv[4 * j + 3] = A.w;
    }
#pragma unroll
    for (int j = 0; j < 16; j++) {
        int idx = pad + (j >> 2) * 1024 + 4 * tid + (j & 3);
        vv[j] -= 0.5f * (float)cb[idx];
    }
    // staged lower bound, then bisect to count in [16,48]
    float lo = -40.f, hi = 0.f;
    {
        int c = 0;
#pragma unroll
        for (int j = 0; j < 16; j++) c += (vv[j] >= lo);
        if (blk_sum(c, s_ws) < 16) {
            hi = lo; lo = -1200.f;
            c = 0;
#pragma unroll
            for (int j = 0; j < 16; j++) c += (vv[j] >= lo);
            if (blk_sum(c, s_ws) < 16) { hi = lo; lo = -3.0e38f; }
        }
    }
    for (int it = 0; it < 24; it++) {
        float mid = 0.5f * (lo + hi);
        int c = 0;
#pragma unroll
        for (int j = 0; j < 16; j++) c += (vv[j] >= mid);
        int tot = blk_sum(c, s_ws);
        if (tot >= 16) { lo = mid; if (tot <= 48) break; }
        else hi = mid;
    }
    float thr = lo;
#pragma unroll
    for (int j = 0; j < 16; j++) {
        if (vv[j] >= thr) {
            int idx = pad + (j >> 2) * 1024 + 4 * tid + (j & 3);
            int p = atomicAdd(&s_cnt, 1);
            if (p < BUFCAP) s_buf[p] = mkkey(vv[j], idx); else s_ovf = 1;
        }
    }
    if (tid < pad) {                                  // [0,pad) scalar prologue
        float a = lp[tid] - 0.5f * (float)cb[tid];
        int p = atomicAdd(&s_cnt, 1);
        if (p < BUFCAP) s_buf[p] = mkkey(a, tid); else s_ovf = 1;
    }

    // ---- stream: warp-autonomous slices, NO barriers in hot loop ----
    int wid = tid >> 5, lane = tid & 31;
    int start0 = pad + 4096;
    int quads_total = (V_ - start0) >> 2;
    int per_w = quads_total >> 3;
    int qi = 1024 + wid * per_w;                      // quad index in lp4 space
    int nq = (wid == 7) ? (quads_total - 7 * per_w - 1) : per_w;
    int qend = qi + nq;

    for (; qi + 256 <= qend; qi += 256) {
        float4 A[8];
#pragma unroll
        for (int j = 0; j < 8; j++) A[j] = lp4[qi + j * 32 + lane];
#pragma unroll
        for (int j = 0; j < 8; j++)
            pquad(A[j], pad + 4 * (qi + j * 32 + lane), thr, cb, s_buf, &s_cnt, &s_ovf);
    }
    for (; qi + 32 <= qend; qi += 32) {
        float4 A = lp4[qi + lane];
        pquad(A, pad + 4 * (qi + lane), thr, cb, s_buf, &s_cnt, &s_ovf);
    }
    if (qi + lane < qend) {
        float4 A = lp4[qi + lane];
        pquad(A, pad + 4 * (qi + lane), thr, cb, s_buf, &s_cnt, &s_ovf);
    }
    if (wid == 7) {                                   // scalar tail incl. EOS
        int sstart = start0 + 4 * (quads_total - 1);
        for (int idx = sstart + lane; idx < V_; idx += 32) {
            float v = lp[idx];
            if (idx == V_ - 1) v -= 1000.0f;
            if (v >= thr) {
                float a = v - 0.5f * (float)cb[idx];
                if (a >= thr) {
                    int p = atomicAdd(&s_cnt, 1);
                    if (p < BUFCAP) s_buf[p] = mkkey(a, idx); else s_ovf = 1;
                }
            }
        }
    }
    __syncthreads();

    // ---- cold exact fallback on overflow (data-independent correctness) ----
    if (s_ovf) {
        if (tid == 0) { s_cnt = 0; s_ovf = 0; }
        __syncthreads();
        float flo = -3.0e38f, fhi = 1.0f;
        for (int it = 0; it < 48; it++) {
            float mid = 0.5f * (flo + fhi);
            int c = 0;
            for (int idx = tid; idx < V_; idx += 256) {
                float v = lp[idx];
                if (idx == V_ - 1) v -= 1000.0f;
                c += ((v - 0.5f * (float)cb[idx]) >= mid);
            }
            int tot = blk_sum(c, s_ws);
            if (tot >= 16) { flo = mid; if (tot <= 1024) break; }
            else fhi = mid;
        }
        for (int idx = tid; idx < V_; idx += 256) {
            float v = lp[idx];
            if (idx == V_ - 1) v -= 1000.0f;
            float a = v - 0.5f * (float)cb[idx];
            if (a >= flo) {
                int p = atomicAdd(&s_cnt, 1);
                if (p < BUFCAP) s_buf[p] = mkkey(a, idx);
            }
        }
        thr = flo;
        __syncthreads();
    }

    // ---- narrow (bisect buffer to <=256) then exact rank selection ----
    int n = s_cnt; if (n > BUFCAP) n = BUFCAP;
    unsigned long long* sel = s_buf;
    int nsel = n;
    if (n > 96) {
        float rlo = thr, rhi = 1.0f;
        int cnt_at_rlo = n;
        for (int it = 0; it < 20; it++) {
            float mid = 0.5f * (rlo + rhi);
            unsigned long long km = ((unsigned long long)ford(mid)) << 32;
            int c = 0;
            for (int p = tid; p < n; p += 256) c += (s_buf[p] >= km);
            int tot = blk_sum(c, s_ws);
            if (tot >= 16) { rlo = mid; cnt_at_rlo = tot; if (tot <= 96) break; }
            else rhi = mid;
        }
        if (cnt_at_rlo <= 256) {
            if (tid == 0) s_cnt2 = 0;
            __syncthreads();
            unsigned long long km = ((unsigned long long)ford(rlo)) << 32;
            for (int p = tid; p < n; p += 256) {
                unsigned long long k = s_buf[p];
                if (k >= km) { int q = atomicAdd(&s_cnt2, 1); if (q < 256) s_b2[q] = k; }
            }
            __syncthreads();
            sel = s_b2;
            nsel = s_cnt2; if (nsel > 256) nsel = 256;
        }
    }
    for (int i = tid; i < nsel; i += 256) {
        unsigned long long k = sel[i];
        int r = 0;
        for (int p = 0; p < nsel; p++) r += (sel[p] > k);
        if (r < 16) g_key[row * 16 + r] = k;
    }
}

// ---------------------------------------------------------------------------
// per-batch global top-16 over 256 candidates; sel_p + history rewrite
__global__ void __launch_bounds__(256) k_select(
        const float* __restrict__ logprobs,
        const void*  __restrict__ beam_seq,
        const float* __restrict__ beam_lps,
        const float* __restrict__ sums,
        const void*  __restrict__ tin,
        float* __restrict__ out) {
    __shared__ unsigned long long s_k2[256];
    __shared__ int s_q[16], s_token[16];
    __shared__ float s_r[16];

    int b = blockIdx.x, tid = threadIdx.x;
    unsigned long long k = g_key[b * 256 + tid];
    float augv = funord((unsigned)(k >> 32));
    int tok = (int)(~(unsigned)k);
    float comb = augv + sums[b * 16 + (tid >> 4)];
    unsigned long long k2 = ((unsigned long long)ford(comb) << 32) | (unsigned)(255 - tid);
    s_k2[tid] = k2;
    __syncthreads();
    int r = 0;
    for (int p = 0; p < 256; p++) r += (s_k2[p] > k2);
    if (r < 16) {
        int q = tid >> 4;
        float rr = logprobs[(size_t)(b * 16 + q) * V_ + tok];
        if (tok == V_ - 1) rr -= 1000.0f;
        s_q[r] = q; s_token[r] = tok; s_r[r] = rr;
        g_q[b * 16 + r] = q;
        out[O2 + b * 16 + r] = comb;
    }
    __syncthreads();

    int is64 = g_is64;
    int t = ((const int*)tin)[0];
    for (int idx = tid; idx < T_ * K_; idx += 256) {
        int rowi = idx >> 4, k2i = idx & 15;
        float sv, lv;
        if (rowi == t) {
            sv = (float)s_token[k2i];
            lv = s_r[k2i];
        } else {
            int kk = (rowi < t) ? s_q[k2i] : k2i;
            int off = (b * T_ + rowi) * K_ + kk;
            sv = is64 ? (float)((const long long*)beam_seq)[off]
                      : (float)((const int*)beam_seq)[off];
            lv = beam_lps[off];
        }
        out[O0 + b * (T_ * K_) + idx] = sv;
        out[O1 + b * (T_ * K_) + idx] = lv;
    }
}

// ---------------------------------------------------------------------------
// state gather: block = 4 rows (grid 2048), thread = 2 float4 (ILP 2)
__global__ void __launch_bounds__(256) k_state(const float* __restrict__ state,
                                               float* __restrict__ out) {
    int n = blockIdx.x * 4 + (threadIdx.x >> 6);   // row in [0, 8192)
    int l64 = threadIdx.x & 63;
    int k  = n & 15;
    int b  = (n >> 4) & 127;
    int sl = n >> 11;
    int q  = g_q[b * 16 + k];
    const float4* src = (const float4*)(state + ((((size_t)sl * B_) + b) * K_ + q) * H_);
    float4*       dst = (float4*)(out + O3 + ((((size_t)sl * B_) + b) * K_ + k) * H_);
    float4 x0 = src[l64];
    float4 x1 = src[l64 + 64];
    dst[l64] = x0;
    dst[l64 + 64] = x1;
}

// ---------------------------------------------------------------------------
extern "C" void kernel_launch(void* const* d_in, const int* in_sizes, int n_in,
                              void* d_out, int out_size) {
    const float* logprobs = (const float*)d_in[0];
    const void*  beam_seq = d_in[1];
    const float* beam_lps = (const float*)d_in[2];
    const float* sums     = (const float*)d_in[3];
    const float* state    = (const float*)d_in[4];
    const void*  prev     = d_in[5];
    const void*  tin      = d_in[6];
    float* out = (float*)d_out;

    k_prep<<<B_, 256>>>(prev, beam_seq);
    k_topk<<<NROW, 256>>>(logprobs);
    k_select<<<B_, 256>>>(logprobs, beam_seq, beam_lps, sums, tin, out);
    k_state<<<(2 * 2 * B_ * K_) / 4, 256>>>(state, out);
}

// round 6
// speedup vs baseline: 2.0334x; 1.0743x over previous
#include <cuda_runtime.h>
#include <cfloat>

#define B_    128
#define K_    16
#define V_    50257
#define T_    20
#define H_    512
#define NROW  2048
#define VPADW 12565

#define O0 0
#define O1 (B_ * T_ * K_)
#define O2 (2 * B_ * T_ * K_)
#define O3 (2 * B_ * T_ * K_ + B_ * K_)

#define BUFCAP   2048
#define THR_INIT (-8.8f)    // heuristic; exact fallback guards correctness

__device__ unsigned int       g_cnt32[B_ * VPADW];  // packed uint8 diversity counts
__device__ unsigned long long g_key[NROW * 16];     // per-row sorted top-16 keys
__device__ int                g_q[B_ * K_];
__device__ int                g_is64;

// ---------------------------------------------------------------------------
__device__ __forceinline__ unsigned ford(float v) {
    unsigned u = __float_as_uint(v);
    return (u & 0x80000000u) ? ~u : (u | 0x80000000u);
}
__device__ __forceinline__ float funord(unsigned u) {
    return __uint_as_float((u & 0x80000000u) ? (u ^ 0x80000000u) : ~u);
}
// key: value desc primary, token asc secondary (larger key = better)
__device__ __forceinline__ unsigned long long mkkey(float v, int tok) {
    return ((unsigned long long)ford(v) << 32) | (unsigned)(~(unsigned)tok);
}

__device__ __forceinline__ int blk_sum(int c, int* s_ws) {
    int tid = threadIdx.x;
    c = (int)__reduce_add_sync(0xffffffffu, (unsigned)c);
    if ((tid & 31) == 0) s_ws[tid >> 5] = c;
    __syncthreads();
    int t = s_ws[0] + s_ws[1] + s_ws[2] + s_ws[3] + s_ws[4] + s_ws[5] + s_ws[6] + s_ws[7];
    __syncthreads();
    return t;
}

// ---------------------------------------------------------------------------
__global__ void __launch_bounds__(256) k_prep(const void* __restrict__ prev,
                                              const void* __restrict__ beam_seq) {
    int b = blockIdx.x, tid = threadIdx.x;
    __shared__ int s_is64;
    if (tid == 0) {
        const long long* p = (const long long*)prev;
        int ok = 1;
        for (int i = 0; i < 8; i++) { long long v = p[i]; if (v < 0 || v >= V_) ok = 0; }
        s_is64 = ok;
        if (b == 0) {
            const long long* q = (const long long*)beam_seq;
            int ok2 = 1;
            for (int i = 0; i < 8; i++) { long long v = q[i]; if (v < 0 || v >= V_) ok2 = 0; }
            g_is64 = ok2;
        }
    }
    unsigned int* c = g_cnt32 + (size_t)b * VPADW;
    for (int i = tid; i < VPADW; i += 256) c[i] = 0u;
    __syncthreads();
    long long v = s_is64 ? ((const long long*)prev)[b * 256 + tid]
                         : (long long)((const int*)prev)[b * 256 + tid];
    int vi = (int)v;
    atomicAdd(&c[vi >> 2], 1u << ((vi & 3) * 8));
}

// ---------------------------------------------------------------------------
__device__ __forceinline__ void pquad(float4 A, int fidx, float thr,
        const unsigned char* __restrict__ cb,
        unsigned long long* s_buf, int* s_cnt, int* s_ovf) {
    float m = fmaxf(fmaxf(A.x, A.y), fmaxf(A.z, A.w));
    if (m < thr) return;
    float v0 = A.x, v1 = A.y, v2 = A.z, v3 = A.w;
    if (v0 >= thr) { float a = v0 - 0.5f * (float)cb[fidx];     if (a >= thr) { int p = atomicAdd(s_cnt, 1); if (p < BUFCAP) s_buf[p] = mkkey(a, fidx);     else *s_ovf = 1; } }
    if (v1 >= thr) { float a = v1 - 0.5f * (float)cb[fidx + 1]; if (a >= thr) { int p = atomicAdd(s_cnt, 1); if (p < BUFCAP) s_buf[p] = mkkey(a, fidx + 1); else *s_ovf = 1; } }
    if (v2 >= thr) { float a = v2 - 0.5f * (float)cb[fidx + 2]; if (a >= thr) { int p = atomicAdd(s_cnt, 1); if (p < BUFCAP) s_buf[p] = mkkey(a, fidx + 2); else *s_ovf = 1; } }
    if (v3 >= thr) { float a = v3 - 0.5f * (float)cb[fidx + 3]; if (a >= thr) { int p = atomicAdd(s_cnt, 1); if (p < BUFCAP) s_buf[p] = mkkey(a, fidx + 3); else *s_ovf = 1; } }
}

// per-row exact top-16 of aug = lp - 0.5*count (EOS -1000 at V-1)
__global__ void __launch_bounds__(256) k_topk(const float* __restrict__ logprobs) {
    __shared__ unsigned long long s_buf[BUFCAP];
    __shared__ unsigned long long s_b2[256];
    __shared__ int s_ws[8];
    __shared__ int s_cnt, s_ovf, s_cnt2;

    int tid = threadIdx.x;
    int row = blockIdx.x;
    int b = row >> 4;
    const float* __restrict__ lp = logprobs + (size_t)row * V_;
    const unsigned char* __restrict__ cb =
        (const unsigned char*)g_cnt32 + (size_t)b * (VPADW * 4);

    int pad = (4 - (row & 3)) & 3;                    // 16B-align float4 stream
    const float4* __restrict__ lp4 = (const float4*)(lp + pad);

    if (tid == 0) { s_cnt = 0; s_ovf = 0; }
    __syncthreads();

    float thr = THR_INIT;

    // ---- single barrier-free stream over the whole row ----
    if (tid < pad) {                                  // [0,pad) scalar prologue
        float a = lp[tid] - 0.5f * (float)cb[tid];
        if (a >= thr) {
            int p = atomicAdd(&s_cnt, 1);
            if (p < BUFCAP) s_buf[p] = mkkey(a, tid); else s_ovf = 1;
        }
    }
    int wid = tid >> 5, lane = tid & 31;
    int quads_total = (V_ - pad) >> 2;
    int per_w = quads_total >> 3;
    int qi = wid * per_w;
    int nq = (wid == 7) ? (quads_total - 7 * per_w - 1) : per_w;
    int qend = qi + nq;

    for (; qi + 256 <= qend; qi += 256) {
        float4 A[8];
#pragma unroll
        for (int j = 0; j < 8; j++) A[j] = __ldcs(&lp4[qi + j * 32 + lane]);
#pragma unroll
        for (int j = 0; j < 8; j++)
            pquad(A[j], pad + 4 * (qi + j * 32 + lane), thr, cb, s_buf, &s_cnt, &s_ovf);
    }
    for (; qi + 32 <= qend; qi += 32) {
        float4 A = __ldcs(&lp4[qi + lane]);
        pquad(A, pad + 4 * (qi + lane), thr, cb, s_buf, &s_cnt, &s_ovf);
    }
    if (qi + lane < qend) {
        float4 A = __ldcs(&lp4[qi + lane]);
        pquad(A, pad + 4 * (qi + lane), thr, cb, s_buf, &s_cnt, &s_ovf);
    }
    if (wid == 7) {                                   // scalar tail incl. EOS
        int sstart = pad + 4 * (quads_total - 1);
        for (int idx = sstart + lane; idx < V_; idx += 32) {
            float v = lp[idx];
            if (idx == V_ - 1) v -= 1000.0f;
            if (v >= thr) {
                float a = v - 0.5f * (float)cb[idx];
                if (a >= thr) {
                    int p = atomicAdd(&s_cnt, 1);
                    if (p < BUFCAP) s_buf[p] = mkkey(a, idx); else s_ovf = 1;
                }
            }
        }
    }
    __syncthreads();

    // ---- cold exact fallback: wrong guess (too high/low) never breaks it ----
    if (s_ovf || s_cnt < 16) {
        int ovf = s_ovf;
        __syncthreads();
        if (tid == 0) { s_cnt = 0; s_ovf = 0; }
        __syncthreads();
        float flo, fhi;
        if (ovf) { flo = thr; fhi = 1.0f; }
        else     { flo = -3.0e38f; fhi = thr; }
        for (int it = 0; it < 48; it++) {
            float mid = 0.5f * (flo + fhi);
            int c = 0;
            for (int idx = tid; idx < V_; idx += 256) {
                float v = lp[idx];
                if (idx == V_ - 1) v -= 1000.0f;
                c += ((v - 0.5f * (float)cb[idx]) >= mid);
            }
            int tot = blk_sum(c, s_ws);
            if (tot >= 16) { flo = mid; if (tot <= 1024) break; }
            else fhi = mid;
        }
        for (int idx = tid; idx < V_; idx += 256) {
            float v = lp[idx];
            if (idx == V_ - 1) v -= 1000.0f;
            float a = v - 0.5f * (float)cb[idx];
            if (a >= flo) {
                int p = atomicAdd(&s_cnt, 1);
                if (p < BUFCAP) s_buf[p] = mkkey(a, idx);
            }
        }
        thr = flo;
        __syncthreads();
    }

    // ---- narrow (only if large) then exact rank selection ----
    int n = s_cnt; if (n > BUFCAP) n = BUFCAP;
    unsigned long long* sel = s_buf;
    int nsel = n;
    if (n > 512) {
        float rlo = thr, rhi = 1.0f;
        int cnt_at_rlo = n;
        for (int it = 0; it < 20; it++) {
            float mid = 0.5f * (rlo + rhi);
            unsigned long long km = ((unsigned long long)ford(mid)) << 32;
            int c = 0;
            for (int p = tid; p < n; p += 256) c += (s_buf[p] >= km);
            int tot = blk_sum(c, s_ws);
            if (tot >= 16) { rlo = mid; cnt_at_rlo = tot; if (tot <= 96) break; }
            else rhi = mid;
        }
        if (cnt_at_rlo <= 256) {
            if (tid == 0) s_cnt2 = 0;
            __syncthreads();
            unsigned long long km = ((unsigned long long)ford(rlo)) << 32;
            for (int p = tid; p < n; p += 256) {
                unsigned long long k = s_buf[p];
                if (k >= km) { int q = atomicAdd(&s_cnt2, 1); if (q < 256) s_b2[q] = k; }
            }
            __syncthreads();
            sel = s_b2;
            nsel = s_cnt2; if (nsel > 256) nsel = 256;
        }
    }
    for (int i = tid; i < nsel; i += 256) {
        unsigned long long k = sel[i];
        int r = 0;
        for (int p = 0; p < nsel; p++) r += (sel[p] > k);
        if (r < 16) g_key[row * 16 + r] = k;
    }
}

// ---------------------------------------------------------------------------
// per-batch global top-16 over 256 candidates; sel_p + history rewrite
__global__ void __launch_bounds__(256) k_select(
        const float* __restrict__ logprobs,
        const void*  __restrict__ beam_seq,
        const float* __restrict__ beam_lps,
        const float* __restrict__ sums,
        const void*  __restrict__ tin,
        float* __restrict__ out) {
    __shared__ unsigned long long s_k2[256];
    __shared__ int s_q[16], s_token[16];
    __shared__ float s_r[16];

    int b = blockIdx.x, tid = threadIdx.x;
    unsigned long long k = g_key[b * 256 + tid];
    float augv = funord((unsigned)(k >> 32));
    int tok = (int)(~(unsigned)k);
    float comb = augv + sums[b * 16 + (tid >> 4)];
    unsigned long long k2 = ((unsigned long long)ford(comb) << 32) | (unsigned)(255 - tid);
    s_k2[tid] = k2;
    __syncthreads();
    int r = 0;
    for (int p = 0; p < 256; p++) r += (s_k2[p] > k2);
    if (r < 16) {
        int q = tid >> 4;
        float rr = logprobs[(size_t)(b * 16 + q) * V_ + tok];
        if (tok == V_ - 1) rr -= 1000.0f;
        s_q[r] = q; s_token[r] = tok; s_r[r] = rr;
        g_q[b * 16 + r] = q;
        out[O2 + b * 16 + r] = comb;
    }
    __syncthreads();

    int is64 = g_is64;
    int t = ((const int*)tin)[0];
    for (int idx = tid; idx < T_ * K_; idx += 256) {
        int rowi = idx >> 4, k2i = idx & 15;
        float sv, lv;
        if (rowi == t) {
            sv = (float)s_token[k2i];
            lv = s_r[k2i];
        } else {
            int kk = (rowi < t) ? s_q[k2i] : k2i;
            int off = (b * T_ + rowi) * K_ + kk;
            sv = is64 ? (float)((const long long*)beam_seq)[off]
                      : (float)((const int*)beam_seq)[off];
            lv = beam_lps[off];
        }
        out[O0 + b * (T_ * K_) + idx] = sv;
        out[O1 + b * (T_ * K_) + idx] = lv;
    }
}

// ---------------------------------------------------------------------------
// state gather: block = 4 rows (grid 2048), thread = 2 float4 (ILP 2)
__global__ void __launch_bounds__(256) k_state(const float* __restrict__ state,
                                               float* __restrict__ out) {
    int n = blockIdx.x * 4 + (threadIdx.x >> 6);   // row in [0, 8192)
    int l64 = threadIdx.x & 63;
    int k  = n & 15;
    int b  = (n >> 4) & 127;
    int sl = n >> 11;
    int q  = g_q[b * 16 + k];
    const float4* src = (const float4*)(state + ((((size_t)sl * B_) + b) * K_ + q) * H_);
    float4*       dst = (float4*)(out + O3 + ((((size_t)sl * B_) + b) * K_ + k) * H_);
    float4 x0 = src[l64];
    float4 x1 = src[l64 + 64];
    dst[l64] = x0;
    dst[l64 + 64] = x1;
}

// ---------------------------------------------------------------------------
extern "C" void kernel_launch(void* const* d_in, const int* in_sizes, int n_in,
                              void* d_out, int out_size) {
    const float* logprobs = (const float*)d_in[0];
    const void*  beam_seq = d_in[1];
    const float* beam_lps = (const float*)d_in[2];
    const float* sums     = (const float*)d_in[3];
    const float* state    = (const float*)d_in[4];
    const void*  prev     = d_in[5];
    const void*  tin      = d_in[6];
    float* out = (float*)d_out;

    k_prep<<<B_, 256>>>(prev, beam_seq);
    k_topk<<<NROW, 256>>>(logprobs);
    k_select<<<B_, 256>>>(logprobs, beam_seq, beam_lps, sums, tin, out);
    k_state<<<(2 * 2 * B_ * K_) / 4, 256>>>(state, out);
}